// round 9
// baseline (speedup 1.0000x reference)
#include <cuda_runtime.h>
#include <cuda_bf16.h>
#include <cstdint>

#define D    512
#define DD   (512 * 512)
#define NSUP 512
#define NQMAX 16384
#define NIT_CHEAP 6
#define NIT_FULL  2
#define NBLK 128

// ---------------- device scratch ----------------
struct ZBlk {                      // zeroed via one cudaMemsetAsync per launch
    unsigned bars[32];
    float fro[2];
    float b[2];
    float w[2][D];
    float mall[D];
    float csum[2][D];
};
__device__ ZBlk g_z;
__device__ float g_mask[NSUP];
__device__ float g_cnt[2];
__device__ float g_G[DD];        // U = Xh^T Xh
__device__ float g_G0[DD];       // W = Xh^T Xl
__device__ float g_A[2 * DD];
__device__ float g_NS0[2 * DD];  // U0/W0 during stats; later X ping-pong
__device__ float g_NS1[2 * DD];
__device__ float g_T[2 * DD];    // V/V0 during stats; later NS temp
__device__ float g_S[2][NQMAX];
__device__ __nv_bfloat16 g_Qh[NQMAX * D];
__device__ __nv_bfloat16 g_Ah[2 * DD];
__device__ __nv_bfloat16 g_Al[2 * DD];
__device__ __nv_bfloat16 g_Th[2 * DD];   // support split Xh pre-spectral; NS temp after
__device__ __nv_bfloat16 g_Tl[2 * DD];
__device__ __nv_bfloat16 g_X0h[2 * DD];
__device__ __nv_bfloat16 g_X0l[2 * DD];
__device__ __nv_bfloat16 g_X1h[2 * DD];
__device__ __nv_bfloat16 g_X1l[2 * DD];

// ---------------- helpers ----------------
__device__ __forceinline__ uint32_t smem_u32(const void* p) {
    uint32_t a;
    asm("{ .reg .u64 t; cvta.to.shared.u64 t, %1; cvt.u32.u64 %0, t; }" : "=r"(a) : "l"(p));
    return a;
}
__device__ __forceinline__ void mma16816(float* d, const uint32_t* a, const uint32_t* b) {
    asm volatile(
        "mma.sync.aligned.m16n8k16.row.col.f32.bf16.bf16.f32 "
        "{%0,%1,%2,%3}, {%4,%5,%6,%7}, {%8,%9}, {%0,%1,%2,%3};"
        : "+f"(d[0]), "+f"(d[1]), "+f"(d[2]), "+f"(d[3])
        : "r"(a[0]), "r"(a[1]), "r"(a[2]), "r"(a[3]), "r"(b[0]), "r"(b[1]));
}
__device__ __forceinline__ void ldm4(uint32_t* r, uint32_t addr) {
    asm volatile("ldmatrix.sync.aligned.m8n8.x4.shared.b16 {%0,%1,%2,%3}, [%4];"
                 : "=r"(r[0]), "=r"(r[1]), "=r"(r[2]), "=r"(r[3]) : "r"(addr));
}
__device__ __forceinline__ void ldm4t(uint32_t* r, uint32_t addr) {
    asm volatile("ldmatrix.sync.aligned.m8n8.x4.trans.shared.b16 {%0,%1,%2,%3}, [%4];"
                 : "=r"(r[0]), "=r"(r[1]), "=r"(r[2]), "=r"(r[3]) : "r"(addr));
}
__device__ __forceinline__ void bf16split2(float v0, float v1, unsigned int& hh, unsigned int& ll) {
    __nv_bfloat16 h0 = __float2bfloat16(v0), h1 = __float2bfloat16(v1);
    __nv_bfloat16 l0 = __float2bfloat16(v0 - __bfloat162float(h0));
    __nv_bfloat16 l1 = __float2bfloat16(v1 - __bfloat162float(h1));
    hh = ((unsigned int)*(unsigned short*)&h0) | (((unsigned int)*(unsigned short*)&h1) << 16);
    ll = ((unsigned int)*(unsigned short*)&l0) | (((unsigned int)*(unsigned short*)&l1) << 16);
}
__device__ __forceinline__ unsigned ld_acq(unsigned* p) {
    unsigned v;
    asm volatile("ld.acquire.gpu.u32 %0, [%1];" : "=r"(v) : "l"(p) : "memory");
    return v;
}
// grid-wide barrier: monotonic counter per barrier slot; all 128 blocks co-resident.
__device__ __forceinline__ void gbar(int k) {
    __syncthreads();
    if (threadIdx.x == 0) {
        __threadfence();
        atomicAdd(&g_z.bars[k], 1u);
        while (ld_acq(&g_z.bars[k]) < (unsigned)NBLK) {}
    }
    __syncthreads();
}

// ---------------- K1: fused split(SF) + mask + counts + per-class sums ----------------
__global__ __launch_bounds__(256) void k_pre(const float* __restrict__ SF,
                                             const unsigned int* __restrict__ labw) {
    int tid = threadIdx.x, bid = blockIdx.x;
    // SF -> bf16 hi/lo split into g_Th/g_Tl (one float4 per thread)
    {
        int i = bid * 256 + tid;
        float4 v = ((const float4*)SF)[i];
        uint2 hh, ll;
        bf16split2(v.x, v.y, hh.x, ll.x);
        bf16split2(v.z, v.w, hh.y, ll.y);
        ((uint2*)g_Th)[i] = hh;
        ((uint2*)g_Tl)[i] = ll;
    }
    if (bid < 16) {
        __shared__ int det;
        __shared__ float m[128];
        __shared__ float red[256];
        if (tid == 0) det = 0;
        __syncthreads();
        for (int w = tid; w < 512; w += 256)
            if ((w & 1) && labw[w]) det = 1;   // benign race; int64 labels have zero odd words
        __syncthreads();
        int rb = (bid >> 2) * 128;
        if (tid < 128) {
            unsigned li = det ? labw[rb + tid] : labw[2 * (rb + tid)];
            m[tid] = (li == 0) ? 1.f : 0.f;
        }
        float csum_loc = 0.f;
        for (int s = tid; s < 512; s += 256) {
            unsigned li = det ? labw[s] : labw[2 * s];
            float mv = (li == 0) ? 1.f : 0.f;
            if (bid == 0) g_mask[s] = mv;
            csum_loc += mv;
        }
        red[tid] = csum_loc;
        __syncthreads();
        for (int s = 128; s > 0; s >>= 1) {
            if (tid < s) red[tid] += red[tid + s];
            __syncthreads();
        }
        if (bid == 0 && tid == 0) { g_cnt[0] = red[0]; g_cnt[1] = (float)NSUP - red[0]; }
        if (tid < 128) {
            int j = (bid & 3) * 128 + tid;
            float sa = 0.f, s0 = 0.f;
            for (int r = 0; r < 128; r++) {
                float x = SF[(size_t)(rb + r) * D + j];
                sa += x; s0 += m[r] * x;
            }
            atomicAdd(&g_z.mall[j], sa);
            atomicAdd(&g_z.csum[0][j], s0);
            atomicAdd(&g_z.csum[1][j], sa - s0);
        }
    }
}

// ---------------- K2: Gram via tensor cores (unchanged from R8) ----------------
#define GTP 144
#define GTT 4608
__global__ __launch_bounds__(256) void k_gram_tc(
    const __nv_bfloat16* __restrict__ Xh, const __nv_bfloat16* __restrict__ Xl,
    float* __restrict__ U, float* __restrict__ W, float* __restrict__ V,
    float* __restrict__ U0, float* __restrict__ W0, float* __restrict__ V0) {
    __shared__ char sm[6 * GTT];
    uint32_t smb = smem_u32(sm);
    const char* Xh8 = (const char*)Xh;
    const char* Xl8 = (const char*)Xl;
    int tid = threadIdx.x, lane = tid & 31, wid = tid >> 5;
    int warp_m = (wid & 3) * 16, warp_n = (wid >> 2) * 32;
    int i0 = blockIdx.x * 64, j0 = blockIdx.y * 64;
    int row = tid >> 3, seg = (tid & 7) * 16;
    float d[6][4][4];
#pragma unroll
    for (int p = 0; p < 6; p++)
#pragma unroll
        for (int n = 0; n < 4; n++)
#pragma unroll
            for (int k = 0; k < 4; k++) d[p][n][k] = 0.f;

    for (int ch = 0; ch < 16; ch++) {
        int r0 = ch * 32;
        float mr = g_mask[r0 + row];
        size_t ro = (size_t)(r0 + row) * 1024;
        uint4 hi = *(const uint4*)(Xh8 + ro + i0 * 2 + seg);
        uint4 li = *(const uint4*)(Xl8 + ro + i0 * 2 + seg);
        uint4 hj = *(const uint4*)(Xh8 + ro + j0 * 2 + seg);
        uint4 lj = *(const uint4*)(Xl8 + ro + j0 * 2 + seg);
        uint4 zz = make_uint4(0u, 0u, 0u, 0u);
        uint4 mhi = (mr > 0.5f) ? hi : zz;
        uint4 mli = (mr > 0.5f) ? li : zz;
        __syncthreads();
        char* base = sm + row * GTP + seg;
        *(uint4*)(base + 0 * GTT) = hi;
        *(uint4*)(base + 1 * GTT) = li;
        *(uint4*)(base + 2 * GTT) = mhi;
        *(uint4*)(base + 3 * GTT) = mli;
        *(uint4*)(base + 4 * GTT) = hj;
        *(uint4*)(base + 5 * GTT) = lj;
        __syncthreads();
#pragma unroll
        for (int ks = 0; ks < 2; ks++) {
            uint32_t fa[4][4];
            uint32_t arow = (uint32_t)(ks * 16 + (lane >> 4) * 8 + (lane & 7)) * GTP
                          + (warp_m + ((lane >> 3) & 1) * 8) * 2;
#pragma unroll
            for (int p = 0; p < 4; p++) ldm4t(fa[p], smb + p * GTT + arow);
            uint32_t fb[2][4][2];
#pragma unroll
            for (int bm = 0; bm < 2; bm++)
#pragma unroll
                for (int nn = 0; nn < 2; nn++) {
                    uint32_t r4[4];
                    uint32_t baddr = smb + (4 + bm) * GTT
                        + (uint32_t)(ks * 16 + ((lane >> 3) & 1) * 8 + (lane & 7)) * GTP
                        + (warp_n + nn * 16 + (lane >> 4) * 8) * 2;
                    ldm4t(r4, baddr);
                    fb[bm][nn * 2][0] = r4[0]; fb[bm][nn * 2][1] = r4[1];
                    fb[bm][nn * 2 + 1][0] = r4[2]; fb[bm][nn * 2 + 1][1] = r4[3];
                }
#pragma unroll
            for (int ni = 0; ni < 4; ni++) {
                mma16816(d[0][ni], fa[0], fb[0][ni]);
                mma16816(d[1][ni], fa[0], fb[1][ni]);
                mma16816(d[2][ni], fa[1], fb[1][ni]);
                mma16816(d[3][ni], fa[2], fb[0][ni]);
                mma16816(d[4][ni], fa[2], fb[1][ni]);
                mma16816(d[5][ni], fa[3], fb[1][ni]);
            }
        }
    }
    float* outs[6] = {U, W, V, U0, W0, V0};
#pragma unroll
    for (int p = 0; p < 6; p++)
#pragma unroll
        for (int ni = 0; ni < 4; ni++) {
            int col = j0 + warp_n + ni * 8 + 2 * (lane & 3);
#pragma unroll
            for (int h = 0; h < 2; h++) {
                int r = i0 + warp_m + h * 8 + (lane >> 2);
                *(float2*)&outs[p][(size_t)r * D + col] =
                    make_float2(d[p][ni][2 * h], d[p][ni][2 * h + 1]);
            }
        }
}

// ---------------- device GEMM phase for the giant NS kernel ----------------
#define NSA 5120
#define NSB 4608
#define NS_BUF (NSA + NSB)
__device__ __noinline__ void ns_gemm_dev(
    char* sm,
    const char* Ah8, const char* Al8, const char* Bh8, const char* Bl8,
    const float* E, float* C, __nv_bfloat16* Ch, __nv_bfloat16* Cl,
    int mode, int nchunks, int accFro, float* froDst) {
    uint32_t smb = smem_u32(sm);
    int tid = threadIdx.x, lane = tid & 31, wid = tid >> 5;
    int warp_m = (wid & 1) * 32, warp_n = (wid >> 1) * 16;
    int i0 = blockIdx.x * 64, j0 = blockIdx.y * 64;
    int ar = tid >> 2, aseg = (tid & 3) * 16;
    int br = tid >> 3, bseg = (tid & 7) * 16;

    float d[2][2][4];
#pragma unroll
    for (int a = 0; a < 2; a++)
#pragma unroll
        for (int b = 0; b < 2; b++)
#pragma unroll
            for (int k = 0; k < 4; k++) d[a][b][k] = 0.f;

    uint4 ra, rb;
#define NS_LOAD(c) do { \
        int p = (c) >> 4; int kb = ((c) & 15) * 64; \
        const char* Asrc = (p == 2) ? Al8 : Ah8; \
        const char* Bsrc = (p == 1) ? Bl8 : Bh8; \
        ra = *(const uint4*)(Asrc + (size_t)(i0 + ar) * 1024 + kb + aseg); \
        rb = *(const uint4*)(Bsrc + (size_t)(((c) & 15) * 32 + br) * 1024 + j0 * 2 + bseg); \
    } while (0)
#define NS_STS(buf) do { \
        *(uint4*)(sm + (buf) * NS_BUF + ar * 80 + aseg) = ra; \
        *(uint4*)(sm + (buf) * NS_BUF + NSA + br * 144 + bseg) = rb; \
    } while (0)

    NS_LOAD(0); NS_STS(0);
    __syncthreads();
    for (int c = 0; c < nchunks; c++) {
        int cur = c & 1;
        if (c < nchunks - 1) NS_LOAD(c + 1);
        uint32_t baseA = smb + cur * NS_BUF;
        uint32_t baseB = baseA + NSA;
#pragma unroll
        for (int ks = 0; ks < 2; ks++) {
            uint32_t afr[2][4], bfr[2][2], r4[4];
#pragma unroll
            for (int mi = 0; mi < 2; mi++)
                ldm4(afr[mi], baseA + (warp_m + mi * 16 + (lane & 15)) * 80 + (lane >> 4) * 16 + ks * 32);
            {
                int rowB = ks * 16 + ((lane >> 3) & 1) * 8 + (lane & 7);
                int colB = warp_n + (lane >> 4) * 8;
                ldm4t(r4, baseB + rowB * 144 + colB * 2);
            }
            bfr[0][0] = r4[0]; bfr[0][1] = r4[1]; bfr[1][0] = r4[2]; bfr[1][1] = r4[3];
#pragma unroll
            for (int mi = 0; mi < 2; mi++)
#pragma unroll
                for (int ni = 0; ni < 2; ni++)
                    mma16816(d[mi][ni], afr[mi], bfr[ni]);
        }
        if (c < nchunks - 1) NS_STS(1 - cur);
        __syncthreads();
    }
    float fsum = 0.f;
#pragma unroll
    for (int mi = 0; mi < 2; mi++)
#pragma unroll
        for (int ni = 0; ni < 2; ni++) {
            int col = j0 + warp_n + ni * 8 + 2 * (lane & 3);
#pragma unroll
            for (int h = 0; h < 2; h++) {
                int row = i0 + warp_m + mi * 16 + h * 8 + (lane >> 2);
                size_t idx = (size_t)row * D + col;
                float v0 = d[mi][ni][2 * h], v1 = d[mi][ni][2 * h + 1];
                if (mode) {
                    float2 e = *(const float2*)&E[idx];
                    v0 = 2.f * e.x - v0; v1 = 2.f * e.y - v1;
                }
                *(float2*)&C[idx] = make_float2(v0, v1);
                unsigned int hh, ll;
                bf16split2(v0, v1, hh, ll);
                *(unsigned int*)&Ch[idx] = hh;
                *(unsigned int*)&Cl[idx] = ll;
                if (accFro) fsum += v0 * v0 + v1 * v1;
            }
        }
    if (accFro) {
        for (int o = 16; o > 0; o >>= 1) fsum += __shfl_down_sync(0xffffffffu, fsum, o);
        if (lane == 0) atomicAdd(froDst, fsum);
    }
#undef NS_LOAD
#undef NS_STS
}

// ---------------- K3: giant NS kernel — assemble, spectral, init, 8 NS iters, w/b ----------------
__global__ __launch_bounds__(256) void k_ns_giant() {
    __shared__ char sm[2 * NS_BUF];
    int tid = threadIdx.x;
    int z = blockIdx.z;
    int i0 = blockIdx.x * 64, j0 = blockIdx.y * 64;
    size_t zo = (size_t)z * DD;
    int bk = 0;

    // --- Phase A: assemble A_c tile (+ bf16 split), means folded in ---
    float nc = g_cnt[z];
    float rnc = 1.f / nc;
    float lam = fminf(nc / (nc + 1.f), 0.1f);
    for (int e = tid; e < 4096; e += 256) {
        int r = e >> 6, cc = e & 63;
        int i = i0 + r, j = j0 + cc;
        int t = i * D + j, tT = j * D + i;
        float g  = g_G[t] + g_T[t] + g_G0[t] + g_G0[tT];
        float g0 = g_NS0[t] + g_T[DD + t] + g_NS0[DD + t] + g_NS0[DD + tT];
        float gc = z ? (g - g0) : g0;
        float mi = g_z.csum[z][i] * rnc, mj = g_z.csum[z][j] * rnc;
        float mai = g_z.mall[i] * (1.f / NSUP), maj = g_z.mall[j] * (1.f / NSUP);
        float covc = (gc - nc * mi * mj) / (nc - 1.f);
        float task = (g - (float)NSUP * mai * maj) / ((float)NSUP - 1.f);
        float a = lam * covc + (1.f - lam) * task + ((i == j) ? 0.1f : 0.f);
        size_t idx = zo + t;
        g_A[idx] = a;
        __nv_bfloat16 h = __float2bfloat16(a);
        g_Ah[idx] = h;
        g_Al[idx] = __float2bfloat16(a - __bfloat162float(h));
    }
    gbar(bk++);

    // --- Phase B: spectral T = A@A (1-pass bf16) with fused fro(A^2)^2 accumulation ---
    ns_gemm_dev(sm, (char*)(g_Ah + zo), (char*)(g_Al + zo), (char*)(g_Ah + zo), (char*)(g_Al + zo),
                nullptr, g_T + zo, g_Th + zo, g_Tl + zo, 0, 16, 1, &g_z.fro[z]);
    gbar(bk++);

    // --- Phase C: quadratic NS init X0 = u*I + v*A ---
    {
        float lub = 1.02f * powf(g_z.fro[z], 0.25f) + 0.02f;  // (sum l^4)^(1/4) >= lmax
        float aa = 0.1f;
        float Ssum = aa * aa + 6.f * aa * lub + lub * lub;
        float u = 8.f * (aa + lub) / Ssum;
        float vv = -8.f / Ssum;
        for (int e = tid; e < 4096; e += 256) {
            int r = e >> 6, cc = e & 63;
            int i = i0 + r, j = j0 + cc;
            size_t idx = zo + i * D + j;
            float v = vv * g_A[idx] + ((i == j) ? u : 0.f);
            g_NS0[idx] = v;
            __nv_bfloat16 h = __float2bfloat16(v);
            g_X0h[idx] = h;
            g_X0l[idx] = __float2bfloat16(v - __bfloat162float(h));
        }
    }
    gbar(bk++);

    // --- Phase D: NS iterations (6 cheap 1-pass, 2 full 3-pass) ---
    float *Xf = g_NS0 + zo, *Xnf = g_NS1 + zo;
    __nv_bfloat16 *Xh = g_X0h + zo, *Xl = g_X0l + zo;
    __nv_bfloat16 *Xnh = g_X1h + zo, *Xnl = g_X1l + zo;
    for (int it = 0; it < NIT_CHEAP + NIT_FULL; it++) {
        int nch = (it < NIT_CHEAP) ? 16 : 48;
        ns_gemm_dev(sm, (char*)Xh, (char*)Xl, (char*)(g_Ah + zo), (char*)(g_Al + zo),
                    nullptr, g_T + zo, g_Th + zo, g_Tl + zo, 0, nch, 0, nullptr);
        gbar(bk++);
        ns_gemm_dev(sm, (char*)(g_Th + zo), (char*)(g_Tl + zo), (char*)Xh, (char*)Xl,
                    Xf, Xnf, Xnh, Xnl, 1, nch, 0, nullptr);
        gbar(bk++);
        float* tf = Xf; Xf = Xnf; Xnf = tf;
        __nv_bfloat16* tb;
        tb = Xh; Xh = Xnh; Xnh = tb;
        tb = Xl; Xl = Xnl; Xnl = tb;
    }
    // 8 iterations (even) -> final X in g_NS0 / g_X0h / g_X0l

    // --- Phase E: partial w = P m for this tile ---
    {
        int r = tid >> 2, q4 = tid & 3;
        const float* row = Xf + (size_t)(i0 + r) * D;
        float s = 0.f;
#pragma unroll
        for (int jj = 0; jj < 16; jj++) {
            int j = j0 + q4 * 16 + jj;
            s += row[j] * (g_z.csum[z][j] * rnc);
        }
        s += __shfl_xor_sync(0xffffffffu, s, 1);
        s += __shfl_xor_sync(0xffffffffu, s, 2);
        if (q4 == 0) atomicAdd(&g_z.w[z][i0 + r], s);
    }
    gbar(bk++);

    // --- Phase F: b = m^T w (one block per class) ---
    if (blockIdx.x == 0 && blockIdx.y == 0) {
        float* red = (float*)sm;
        float s = 0.f;
        for (int i = tid; i < D; i += 256)
            s += g_z.w[z][i] * (g_z.csum[z][i] * rnc);
        red[tid] = s;
        __syncthreads();
        for (int st = 128; st > 0; st >>= 1) {
            if (tid < st) red[tid] += red[tid + st];
            __syncthreads();
        }
        if (tid == 0) g_z.b[z] = red[0];
    }
}

// ---------------- Q split fp32 -> bf16 hi only ----------------
__global__ void k_split(const float* __restrict__ S, __nv_bfloat16* __restrict__ H) {
    int i = blockIdx.x * 256 + threadIdx.x;
    float4 v = ((const float4*)S)[i];
    __nv_bfloat16 h0 = __float2bfloat16(v.x), h1 = __float2bfloat16(v.y);
    __nv_bfloat16 h2 = __float2bfloat16(v.z), h3 = __float2bfloat16(v.w);
    uint2 hh;
    hh.x = ((unsigned int)*(unsigned short*)&h0) | (((unsigned int)*(unsigned short*)&h1) << 16);
    hh.y = ((unsigned int)*(unsigned short*)&h2) | (((unsigned int)*(unsigned short*)&h3) << 16);
    ((uint2*)H)[i] = hh;
}

// ---------------- K4: main pass, 2-pass: H = Qh@(Ph+Pl); S = H . (2q - bf16(q)) ----------------
#define MB_BUF 20480
__global__ __launch_bounds__(256, 2) void k_main_mma(
    const float* __restrict__ Q,
    const __nv_bfloat16* __restrict__ Qh,
    const __nv_bfloat16* __restrict__ Phg, const __nv_bfloat16* __restrict__ Plg) {
    extern __shared__ char sm[];
    __shared__ float sRow[128][2];
    int cls = blockIdx.y;
    const char* Ph8 = (const char*)(Phg + (size_t)cls * DD);
    const char* Pl8 = (const char*)(Plg + (size_t)cls * DD);
    const char* Qh8 = (const char*)Qh;
    uint32_t smb = smem_u32(sm);
    int tid = threadIdx.x, lane = tid & 31, wid = tid >> 5;
    int warp_m = (wid >> 1) * 32, warp_n = (wid & 1) * 64;
    int q0 = blockIdx.x * 128;
    int r0 = tid >> 2, cseg = (tid & 3) * 16;
    float accS[4] = {0.f, 0.f, 0.f, 0.f};
    uint4 ra0, ra1, rb0, rb1;

#define MB_LOAD(c, n0) do { \
        int p = (c) >> 4; int kb = ((c) & 15) * 64 + cseg; \
        const char* Bsrc = p ? Pl8 : Ph8; \
        ra0 = *(const uint4*)(Qh8 + (size_t)(q0 + r0) * 1024 + kb); \
        ra1 = *(const uint4*)(Qh8 + (size_t)(q0 + 64 + r0) * 1024 + kb); \
        rb0 = *(const uint4*)(Bsrc + (size_t)((n0) + r0) * 1024 + kb); \
        rb1 = *(const uint4*)(Bsrc + (size_t)((n0) + 64 + r0) * 1024 + kb); \
    } while (0)
#define MB_STS(buf) do { \
        char* dA = sm + (buf) * MB_BUF + r0 * 80 + cseg; \
        *(uint4*)dA = ra0; *(uint4*)(dA + 64 * 80) = ra1; \
        char* dB = sm + (buf) * MB_BUF + 10240 + r0 * 80 + cseg; \
        *(uint4*)dB = rb0; *(uint4*)(dB + 64 * 80) = rb1; \
    } while (0)

    for (int nt = 0; nt < 4; nt++) {
        int n0 = nt * 128;
        float d[2][8][4];
#pragma unroll
        for (int a = 0; a < 2; a++)
#pragma unroll
            for (int b = 0; b < 8; b++)
#pragma unroll
                for (int k = 0; k < 4; k++) d[a][b][k] = 0.f;
        MB_LOAD(0, n0); MB_STS(0);
        __syncthreads();
        for (int c = 0; c < 32; c++) {
            int cur = c & 1;
            if (c < 31) MB_LOAD(c + 1, n0);
            uint32_t baseA = smb + cur * MB_BUF;
            uint32_t baseB = baseA + 10240;
#pragma unroll
            for (int ks = 0; ks < 2; ks++) {
                uint32_t afr[2][4], bfr[8][2], r4[4];
#pragma unroll
                for (int mi = 0; mi < 2; mi++)
                    ldm4(afr[mi], baseA + (warp_m + mi * 16 + (lane & 15)) * 80 + (lane >> 4) * 16 + ks * 32);
#pragma unroll
                for (int j = 0; j < 4; j++) {
                    ldm4(r4, baseB + (warp_n + j * 16 + ((lane >> 4) & 1) * 8 + (lane & 7)) * 80 + ((lane >> 3) & 1) * 16 + ks * 32);
                    bfr[2 * j][0] = r4[0]; bfr[2 * j][1] = r4[1];
                    bfr[2 * j + 1][0] = r4[2]; bfr[2 * j + 1][1] = r4[3];
                }
#pragma unroll
                for (int mi = 0; mi < 2; mi++)
#pragma unroll
                    for (int ni = 0; ni < 8; ni++)
                        mma16816(d[mi][ni], afr[mi], bfr[ni]);
            }
            if (c < 31) MB_STS(1 - cur);
            __syncthreads();
        }
#pragma unroll
        for (int mi = 0; mi < 2; mi++)
#pragma unroll
            for (int h = 0; h < 2; h++) {
                int row = q0 + warp_m + mi * 16 + h * 8 + (lane >> 2);
                float a = 0.f;
#pragma unroll
                for (int ni = 0; ni < 8; ni++) {
                    int col = n0 + warp_n + ni * 8 + 2 * (lane & 3);
                    float2 qv = *(const float2*)&Q[(size_t)row * D + col];
                    float v0 = 2.f * qv.x - __bfloat162float(__float2bfloat16(qv.x));
                    float v1 = 2.f * qv.y - __bfloat162float(__float2bfloat16(qv.y));
                    a += d[mi][ni][2 * h] * v0 + d[mi][ni][2 * h + 1] * v1;
                }
                accS[mi * 2 + h] += a;
            }
    }
#pragma unroll
    for (int i = 0; i < 4; i++) {
        accS[i] += __shfl_xor_sync(0xffffffffu, accS[i], 1);
        accS[i] += __shfl_xor_sync(0xffffffffu, accS[i], 2);
    }
    if ((lane & 3) == 0) {
#pragma unroll
        for (int mi = 0; mi < 2; mi++)
#pragma unroll
            for (int h = 0; h < 2; h++)
                sRow[warp_m + mi * 16 + h * 8 + (lane >> 2)][wid & 1] = accS[mi * 2 + h];
    }
    __syncthreads();
    if (tid < 128) g_S[cls][q0 + tid] = sRow[tid][0] + sRow[tid][1];
#undef MB_LOAD
#undef MB_STS
}

// ---------------- K5: logits ----------------
__global__ void k_final(const float* __restrict__ Q, float* __restrict__ out, int nq) {
    int w = (blockIdx.x * blockDim.x + threadIdx.x) >> 5;
    int lane = threadIdx.x & 31;
    if (w >= nq) return;
    float qw0 = 0.f, qw1 = 0.f;
    for (int k = lane; k < D; k += 32) {
        float qk = Q[w * D + k];
        qw0 += qk * g_z.w[0][k];
        qw1 += qk * g_z.w[1][k];
    }
    for (int o = 16; o > 0; o >>= 1) {
        qw0 += __shfl_down_sync(0xffffffffu, qw0, o);
        qw1 += __shfl_down_sync(0xffffffffu, qw1, o);
    }
    if (lane == 0) {
        out[w * 2 + 0] = -(g_S[0][w] - 2.f * qw0 + g_z.b[0]);
        out[w * 2 + 1] = -(g_S[1][w] - 2.f * qw1 + g_z.b[1]);
    }
}

// ---------------- launch ----------------
extern "C" void kernel_launch(void* const* d_in, const int* in_sizes, int n_in,
                              void* d_out, int out_size) {
    const float*        SF   = (const float*)d_in[0];
    const unsigned int* labw = (const unsigned int*)d_in[1];
    const float*        Q    = (const float*)d_in[2];
    float*              out  = (float*)d_out;
    int nq = in_sizes[2] / D;  // 16384

    void* pZ;
    float *pT, *pG, *pG0, *pX0;
    __nv_bfloat16 *pQh, *pTh, *pTl, *pXh0, *pXl0;
    cudaGetSymbolAddress(&pZ, g_z);
    cudaGetSymbolAddress((void**)&pT, g_T);
    cudaGetSymbolAddress((void**)&pG, g_G);
    cudaGetSymbolAddress((void**)&pG0, g_G0);
    cudaGetSymbolAddress((void**)&pX0, g_NS0);
    cudaGetSymbolAddress((void**)&pQh, g_Qh);
    cudaGetSymbolAddress((void**)&pTh, g_Th);
    cudaGetSymbolAddress((void**)&pTl, g_Tl);
    cudaGetSymbolAddress((void**)&pXh0, g_X0h);
    cudaGetSymbolAddress((void**)&pXl0, g_X0l);
    cudaFuncSetAttribute(k_main_mma, cudaFuncAttributeMaxDynamicSharedMemorySize, 2 * MB_BUF);

    cudaMemsetAsync(pZ, 0, sizeof(ZBlk));
    k_pre<<<256, 256>>>(SF, labw);
    k_gram_tc<<<dim3(8, 8), 256>>>(pTh, pTl, pG, pG0, pT, pX0, pX0 + DD, pT + DD);
    k_ns_giant<<<dim3(8, 8, 2), 256>>>();
    k_split<<<(nq * D) / 1024, 256>>>(Q, pQh);
    k_main_mma<<<dim3(nq / 128, 2), 256, 2 * MB_BUF>>>(Q, pQh, pXh0, pXl0);
    k_final<<<(nq * 32 + 255) / 256, 256>>>(Q, out, nq);
}

// round 11
// speedup vs baseline: 1.2277x; 1.2277x over previous
#include <cuda_runtime.h>
#include <cuda_bf16.h>
#include <cstdint>
#include <cstddef>

#define D    512
#define DD   (512 * 512)
#define NSUP 512
#define NQMAX 16384
#define NIT_CHEAP 5
#define NIT_FULL  1

// ---------------- device scratch ----------------
struct ZBlk {                      // zeroed via one cudaMemsetAsync per launch
    float fro[2];
    float b[2];
    float mall[D];
    float csum[2][D];
};
__device__ ZBlk g_z;
__device__ float g_mask[NSUP];
__device__ float g_cnt[2];
__device__ float g_G[DD];        // U = Xh^T Xh
__device__ float g_G0[DD];       // W = Xh^T Xl
__device__ float g_A[2 * DD];
__device__ float g_NS0[2 * DD];  // U0/W0 during stats; later X ping-pong
__device__ float g_NS1[2 * DD];
__device__ float g_T[2 * DD];    // V/V0 during stats; later NS temp
__device__ float g_w[2][D];
__device__ float g_S[2][NQMAX];
__device__ __nv_bfloat16 g_Qh[NQMAX * D];
__device__ __nv_bfloat16 g_Ah[2 * DD];
__device__ __nv_bfloat16 g_Al[2 * DD];
__device__ __nv_bfloat16 g_Th[2 * DD];   // support split Xh pre-spectral; NS temp after
__device__ __nv_bfloat16 g_Tl[2 * DD];
__device__ __nv_bfloat16 g_X0h[2 * DD];
__device__ __nv_bfloat16 g_X0l[2 * DD];
__device__ __nv_bfloat16 g_X1h[2 * DD];
__device__ __nv_bfloat16 g_X1l[2 * DD];

// ---------------- helpers ----------------
__device__ __forceinline__ uint32_t smem_u32(const void* p) {
    uint32_t a;
    asm("{ .reg .u64 t; cvta.to.shared.u64 t, %1; cvt.u32.u64 %0, t; }" : "=r"(a) : "l"(p));
    return a;
}
__device__ __forceinline__ void mma16816(float* d, const uint32_t* a, const uint32_t* b) {
    asm volatile(
        "mma.sync.aligned.m16n8k16.row.col.f32.bf16.bf16.f32 "
        "{%0,%1,%2,%3}, {%4,%5,%6,%7}, {%8,%9}, {%0,%1,%2,%3};"
        : "+f"(d[0]), "+f"(d[1]), "+f"(d[2]), "+f"(d[3])
        : "r"(a[0]), "r"(a[1]), "r"(a[2]), "r"(a[3]), "r"(b[0]), "r"(b[1]));
}
__device__ __forceinline__ void ldm4(uint32_t* r, uint32_t addr) {
    asm volatile("ldmatrix.sync.aligned.m8n8.x4.shared.b16 {%0,%1,%2,%3}, [%4];"
                 : "=r"(r[0]), "=r"(r[1]), "=r"(r[2]), "=r"(r[3]) : "r"(addr));
}
__device__ __forceinline__ void ldm4t(uint32_t* r, uint32_t addr) {
    asm volatile("ldmatrix.sync.aligned.m8n8.x4.trans.shared.b16 {%0,%1,%2,%3}, [%4];"
                 : "=r"(r[0]), "=r"(r[1]), "=r"(r[2]), "=r"(r[3]) : "r"(addr));
}
__device__ __forceinline__ void bf16split2(float v0, float v1, unsigned int& hh, unsigned int& ll) {
    __nv_bfloat16 h0 = __float2bfloat16(v0), h1 = __float2bfloat16(v1);
    __nv_bfloat16 l0 = __float2bfloat16(v0 - __bfloat162float(h0));
    __nv_bfloat16 l1 = __float2bfloat16(v1 - __bfloat162float(h1));
    hh = ((unsigned int)*(unsigned short*)&h0) | (((unsigned int)*(unsigned short*)&h1) << 16);
    ll = ((unsigned int)*(unsigned short*)&l0) | (((unsigned int)*(unsigned short*)&l1) << 16);
}

// ---------------- K1: fused split(SF) + mask + counts + per-class sums ----------------
__global__ __launch_bounds__(256) void k_pre(const float* __restrict__ SF,
                                             const unsigned int* __restrict__ labw) {
    int tid = threadIdx.x, bid = blockIdx.x;
    // SF -> bf16 hi/lo split into g_Th/g_Tl (one float4 per thread)
    {
        int i = bid * 256 + tid;
        float4 v = ((const float4*)SF)[i];
        uint2 hh, ll;
        bf16split2(v.x, v.y, hh.x, ll.x);
        bf16split2(v.z, v.w, hh.y, ll.y);
        ((uint2*)g_Th)[i] = hh;
        ((uint2*)g_Tl)[i] = ll;
    }
    if (bid < 16) {
        __shared__ int det;
        __shared__ float m[128];
        __shared__ float red[256];
        if (tid == 0) det = 0;
        __syncthreads();
        for (int w = tid; w < 512; w += 256)
            if ((w & 1) && labw[w]) det = 1;   // benign race; int64 labels have zero odd words
        __syncthreads();
        int rb = (bid >> 2) * 128;
        if (tid < 128) {
            unsigned li = det ? labw[rb + tid] : labw[2 * (rb + tid)];
            m[tid] = (li == 0) ? 1.f : 0.f;
        }
        float csum_loc = 0.f;
        for (int s = tid; s < 512; s += 256) {
            unsigned li = det ? labw[s] : labw[2 * s];
            float mv = (li == 0) ? 1.f : 0.f;
            if (bid == 0) g_mask[s] = mv;
            csum_loc += mv;
        }
        red[tid] = csum_loc;
        __syncthreads();
        for (int s = 128; s > 0; s >>= 1) {
            if (tid < s) red[tid] += red[tid + s];
            __syncthreads();
        }
        if (bid == 0 && tid == 0) { g_cnt[0] = red[0]; g_cnt[1] = (float)NSUP - red[0]; }
        if (tid < 128) {
            int j = (bid & 3) * 128 + tid;
            float sa = 0.f, s0 = 0.f;
            for (int r = 0; r < 128; r++) {
                float x = SF[(size_t)(rb + r) * D + j];
                sa += x; s0 += m[r] * x;
            }
            atomicAdd(&g_z.mall[j], sa);
            atomicAdd(&g_z.csum[0][j], s0);
            atomicAdd(&g_z.csum[1][j], sa - s0);
        }
    }
}

// ---------------- K2: Gram via tensor cores ----------------
#define GTP 144
#define GTT 4608
__global__ __launch_bounds__(256) void k_gram_tc(
    const __nv_bfloat16* __restrict__ Xh, const __nv_bfloat16* __restrict__ Xl,
    float* __restrict__ U, float* __restrict__ W, float* __restrict__ V,
    float* __restrict__ U0, float* __restrict__ W0, float* __restrict__ V0) {
    __shared__ char sm[6 * GTT];
    uint32_t smb = smem_u32(sm);
    const char* Xh8 = (const char*)Xh;
    const char* Xl8 = (const char*)Xl;
    int tid = threadIdx.x, lane = tid & 31, wid = tid >> 5;
    int warp_m = (wid & 3) * 16, warp_n = (wid >> 2) * 32;
    int i0 = blockIdx.x * 64, j0 = blockIdx.y * 64;
    int row = tid >> 3, seg = (tid & 7) * 16;
    float d[6][4][4];
#pragma unroll
    for (int p = 0; p < 6; p++)
#pragma unroll
        for (int n = 0; n < 4; n++)
#pragma unroll
            for (int k = 0; k < 4; k++) d[p][n][k] = 0.f;

    for (int ch = 0; ch < 16; ch++) {
        int r0 = ch * 32;
        float mr = g_mask[r0 + row];
        size_t ro = (size_t)(r0 + row) * 1024;
        uint4 hi = *(const uint4*)(Xh8 + ro + i0 * 2 + seg);
        uint4 li = *(const uint4*)(Xl8 + ro + i0 * 2 + seg);
        uint4 hj = *(const uint4*)(Xh8 + ro + j0 * 2 + seg);
        uint4 lj = *(const uint4*)(Xl8 + ro + j0 * 2 + seg);
        uint4 zz = make_uint4(0u, 0u, 0u, 0u);
        uint4 mhi = (mr > 0.5f) ? hi : zz;
        uint4 mli = (mr > 0.5f) ? li : zz;
        __syncthreads();
        char* base = sm + row * GTP + seg;
        *(uint4*)(base + 0 * GTT) = hi;
        *(uint4*)(base + 1 * GTT) = li;
        *(uint4*)(base + 2 * GTT) = mhi;
        *(uint4*)(base + 3 * GTT) = mli;
        *(uint4*)(base + 4 * GTT) = hj;
        *(uint4*)(base + 5 * GTT) = lj;
        __syncthreads();
#pragma unroll
        for (int ks = 0; ks < 2; ks++) {
            uint32_t fa[4][4];
            uint32_t arow = (uint32_t)(ks * 16 + (lane >> 4) * 8 + (lane & 7)) * GTP
                          + (warp_m + ((lane >> 3) & 1) * 8) * 2;
#pragma unroll
            for (int p = 0; p < 4; p++) ldm4t(fa[p], smb + p * GTT + arow);
            uint32_t fb[2][4][2];
#pragma unroll
            for (int bm = 0; bm < 2; bm++)
#pragma unroll
                for (int nn = 0; nn < 2; nn++) {
                    uint32_t r4[4];
                    uint32_t baddr = smb + (4 + bm) * GTT
                        + (uint32_t)(ks * 16 + ((lane >> 3) & 1) * 8 + (lane & 7)) * GTP
                        + (warp_n + nn * 16 + (lane >> 4) * 8) * 2;
                    ldm4t(r4, baddr);
                    fb[bm][nn * 2][0] = r4[0]; fb[bm][nn * 2][1] = r4[1];
                    fb[bm][nn * 2 + 1][0] = r4[2]; fb[bm][nn * 2 + 1][1] = r4[3];
                }
#pragma unroll
            for (int ni = 0; ni < 4; ni++) {
                mma16816(d[0][ni], fa[0], fb[0][ni]);
                mma16816(d[1][ni], fa[0], fb[1][ni]);
                mma16816(d[2][ni], fa[1], fb[1][ni]);
                mma16816(d[3][ni], fa[2], fb[0][ni]);
                mma16816(d[4][ni], fa[2], fb[1][ni]);
                mma16816(d[5][ni], fa[3], fb[1][ni]);
            }
        }
    }
    float* outs[6] = {U, W, V, U0, W0, V0};
#pragma unroll
    for (int p = 0; p < 6; p++)
#pragma unroll
        for (int ni = 0; ni < 4; ni++) {
            int col = j0 + warp_n + ni * 8 + 2 * (lane & 3);
#pragma unroll
            for (int h = 0; h < 2; h++) {
                int r = i0 + warp_m + h * 8 + (lane >> 2);
                *(float2*)&outs[p][(size_t)r * D + col] =
                    make_float2(d[p][ni][2 * h], d[p][ni][2 * h + 1]);
            }
        }
}

// ---------------- K3: assemble A_c (+ bf16 split), means inline ----------------
__global__ void k_assemble() {
    int c = blockIdx.y;
    int t = blockIdx.x * 256 + threadIdx.x;
    int i = t >> 9, j = t & (D - 1);
    int tT = j * D + i;
    float g  = g_G[t] + g_T[t] + g_G0[t] + g_G0[tT];
    float g0 = g_NS0[t] + g_T[DD + t] + g_NS0[DD + t] + g_NS0[DD + tT];
    float gc = c ? (g - g0) : g0;
    float nc = g_cnt[c];
    float rnc = 1.f / nc;
    float mi = g_z.csum[c][i] * rnc, mj = g_z.csum[c][j] * rnc;
    float mai = g_z.mall[i] * (1.f / NSUP), maj = g_z.mall[j] * (1.f / NSUP);
    float covc = (gc - nc * mi * mj) / (nc - 1.f);
    float task = (g - (float)NSUP * mai * maj) / ((float)NSUP - 1.f);
    float lam = fminf(nc / (nc + 1.f), 0.1f);
    float a = lam * covc + (1.f - lam) * task + ((i == j) ? 0.1f : 0.f);
    int idx = c * DD + t;
    g_A[idx] = a;
    __nv_bfloat16 h = __float2bfloat16(a);
    g_Ah[idx] = h;
    g_Al[idx] = __float2bfloat16(a - __bfloat162float(h));
}

// ---------------- K4: quadratic NS init X0 = u*I + v*A (+ split) ----------------
__global__ void k_init() {
    int c = blockIdx.y;
    int t = blockIdx.x * 256 + threadIdx.x;
    int i = t >> 9, j = t & (D - 1);
    float lub = 1.02f * powf(g_z.fro[c], 0.125f) + 0.02f;  // (sum l^8)^(1/8) >= lmax
    float aa = 0.1f;
    float Ssum = aa * aa + 6.f * aa * lub + lub * lub;
    float u = 8.f * (aa + lub) / Ssum;
    float vv = -8.f / Ssum;
    int idx = c * DD + t;
    float v = vv * g_A[idx] + ((i == j) ? u : 0.f);
    g_NS0[idx] = v;
    __nv_bfloat16 h = __float2bfloat16(v);
    g_X0h[idx] = h;
    g_X0l[idx] = __float2bfloat16(v - __bfloat162float(h));
}

// ---------------- NS GEMM: C = A@B (mode0) or 2E - A@B (mode1), + bf16 split out ----------------
// optional fused Frobenius^2 accumulation of C into froDst[blockIdx.z]
#define NSA 5120
#define NSB 4608
#define NS_BUF (NSA + NSB)
__global__ __launch_bounds__(256) void gemm_ns(
    const __nv_bfloat16* __restrict__ Ahp, const __nv_bfloat16* __restrict__ Alp,
    const __nv_bfloat16* __restrict__ Bhp, const __nv_bfloat16* __restrict__ Blp,
    const float* __restrict__ E, float* __restrict__ C,
    __nv_bfloat16* __restrict__ Ch, __nv_bfloat16* __restrict__ Cl,
    int mode, int nchunks, int accFro, float* froDst) {
    __shared__ char sm[2 * NS_BUF];
    size_t zo = (size_t)blockIdx.z * DD;
    const char* Ah8 = (const char*)(Ahp + zo);
    const char* Al8 = (const char*)(Alp + zo);
    const char* Bh8 = (const char*)(Bhp + zo);
    const char* Bl8 = (const char*)(Blp + zo);
    E += zo; C += zo; Ch += zo; Cl += zo;
    uint32_t smb = smem_u32(sm);
    int tid = threadIdx.x, lane = tid & 31, wid = tid >> 5;
    int warp_m = (wid & 1) * 32, warp_n = (wid >> 1) * 16;
    int i0 = blockIdx.x * 64, j0 = blockIdx.y * 64;
    int ar = tid >> 2, aseg = (tid & 3) * 16;
    int br = tid >> 3, bseg = (tid & 7) * 16;

    float d[2][2][4];
#pragma unroll
    for (int a = 0; a < 2; a++)
#pragma unroll
        for (int b = 0; b < 2; b++)
#pragma unroll
            for (int k = 0; k < 4; k++) d[a][b][k] = 0.f;

    uint4 ra, rb;
#define NS_LOAD(c) do { \
        int p = (c) >> 4; int kb = ((c) & 15) * 64; \
        const char* Asrc = (p == 2) ? Al8 : Ah8; \
        const char* Bsrc = (p == 1) ? Bl8 : Bh8; \
        ra = *(const uint4*)(Asrc + (size_t)(i0 + ar) * 1024 + kb + aseg); \
        rb = *(const uint4*)(Bsrc + (size_t)(((c) & 15) * 32 + br) * 1024 + j0 * 2 + bseg); \
    } while (0)
#define NS_STS(buf) do { \
        *(uint4*)(sm + (buf) * NS_BUF + ar * 80 + aseg) = ra; \
        *(uint4*)(sm + (buf) * NS_BUF + NSA + br * 144 + bseg) = rb; \
    } while (0)

    NS_LOAD(0); NS_STS(0);
    __syncthreads();
    for (int c = 0; c < nchunks; c++) {
        int cur = c & 1;
        if (c < nchunks - 1) NS_LOAD(c + 1);
        uint32_t baseA = smb + cur * NS_BUF;
        uint32_t baseB = baseA + NSA;
#pragma unroll
        for (int ks = 0; ks < 2; ks++) {
            uint32_t afr[2][4], bfr[2][2], r4[4];
#pragma unroll
            for (int mi = 0; mi < 2; mi++)
                ldm4(afr[mi], baseA + (warp_m + mi * 16 + (lane & 15)) * 80 + (lane >> 4) * 16 + ks * 32);
            {
                int rowB = ks * 16 + ((lane >> 3) & 1) * 8 + (lane & 7);
                int colB = warp_n + (lane >> 4) * 8;
                ldm4t(r4, baseB + rowB * 144 + colB * 2);
            }
            bfr[0][0] = r4[0]; bfr[0][1] = r4[1]; bfr[1][0] = r4[2]; bfr[1][1] = r4[3];
#pragma unroll
            for (int mi = 0; mi < 2; mi++)
#pragma unroll
                for (int ni = 0; ni < 2; ni++)
                    mma16816(d[mi][ni], afr[mi], bfr[ni]);
        }
        if (c < nchunks - 1) NS_STS(1 - cur);
        __syncthreads();
    }
    float fsum = 0.f;
#pragma unroll
    for (int mi = 0; mi < 2; mi++)
#pragma unroll
        for (int ni = 0; ni < 2; ni++) {
            int col = j0 + warp_n + ni * 8 + 2 * (lane & 3);
#pragma unroll
            for (int h = 0; h < 2; h++) {
                int row = i0 + warp_m + mi * 16 + h * 8 + (lane >> 2);
                size_t idx = (size_t)row * D + col;
                float v0 = d[mi][ni][2 * h], v1 = d[mi][ni][2 * h + 1];
                if (mode) {
                    float2 e = *(const float2*)&E[idx];
                    v0 = 2.f * e.x - v0; v1 = 2.f * e.y - v1;
                }
                *(float2*)&C[idx] = make_float2(v0, v1);
                unsigned int hh, ll;
                bf16split2(v0, v1, hh, ll);
                *(unsigned int*)&Ch[idx] = hh;
                *(unsigned int*)&Cl[idx] = ll;
                if (accFro) fsum += v0 * v0 + v1 * v1;
            }
        }
    if (accFro) {
        for (int o = 16; o > 0; o >>= 1) fsum += __shfl_down_sync(0xffffffffu, fsum, o);
        if (lane == 0) atomicAdd(&froDst[blockIdx.z], fsum);
    }
#undef NS_LOAD
#undef NS_STS
}

// ---------------- K5: w_c = P_c m_c (row-dots, P symmetric), b_c = m^T w ----------------
__global__ void k_wb(const float* __restrict__ P) {
    int c = blockIdx.x;
    int rg = blockIdx.y;
    __shared__ float smean[D];
    int tid = threadIdx.x, lane = tid & 31, wid = tid >> 5;
    float rnc = 1.f / g_cnt[c];
    for (int k = tid; k < D; k += 256) smean[k] = g_z.csum[c][k] * rnc;
    __syncthreads();
    float bpart = 0.f;
    for (int rr = 0; rr < 8; rr++) {
        int r = rg * 64 + wid * 8 + rr;
        const float* row = P + (size_t)c * DD + (size_t)r * D;
        float s = 0.f;
        for (int k = lane; k < D; k += 32) s += row[k] * smean[k];
        for (int o = 16; o > 0; o >>= 1) s += __shfl_down_sync(0xffffffffu, s, o);
        if (lane == 0) { g_w[c][r] = s; bpart += s * smean[r]; }
    }
    if (lane == 0) atomicAdd(&g_z.b[c], bpart);
}

// ---------------- Q split fp32 -> bf16 hi only ----------------
__global__ void k_split(const float* __restrict__ S, __nv_bfloat16* __restrict__ H) {
    int i = blockIdx.x * 256 + threadIdx.x;
    float4 v = ((const float4*)S)[i];
    __nv_bfloat16 h0 = __float2bfloat16(v.x), h1 = __float2bfloat16(v.y);
    __nv_bfloat16 h2 = __float2bfloat16(v.z), h3 = __float2bfloat16(v.w);
    uint2 hh;
    hh.x = ((unsigned int)*(unsigned short*)&h0) | (((unsigned int)*(unsigned short*)&h1) << 16);
    hh.y = ((unsigned int)*(unsigned short*)&h2) | (((unsigned int)*(unsigned short*)&h3) << 16);
    ((uint2*)H)[i] = hh;
}

// ---------------- K6: main pass, 2-pass: H = Qh@(Ph+Pl); S = H . (2q - bf16(q)) ----------------
#define MB_BUF 20480
__global__ __launch_bounds__(256, 2) void k_main_mma(
    const float* __restrict__ Q,
    const __nv_bfloat16* __restrict__ Qh,
    const __nv_bfloat16* __restrict__ Phg, const __nv_bfloat16* __restrict__ Plg) {
    extern __shared__ char sm[];
    __shared__ float sRow[128][2];
    int cls = blockIdx.y;
    const char* Ph8 = (const char*)(Phg + (size_t)cls * DD);
    const char* Pl8 = (const char*)(Plg + (size_t)cls * DD);
    const char* Qh8 = (const char*)Qh;
    uint32_t smb = smem_u32(sm);
    int tid = threadIdx.x, lane = tid & 31, wid = tid >> 5;
    int warp_m = (wid >> 1) * 32, warp_n = (wid & 1) * 64;
    int q0 = blockIdx.x * 128;
    int r0 = tid >> 2, cseg = (tid & 3) * 16;
    float accS[4] = {0.f, 0.f, 0.f, 0.f};
    uint4 ra0, ra1, rb0, rb1;

#define MB_LOAD(c, n0) do { \
        int p = (c) >> 4; int kb = ((c) & 15) * 64 + cseg; \
        const char* Bsrc = p ? Pl8 : Ph8; \
        ra0 = *(const uint4*)(Qh8 + (size_t)(q0 + r0) * 1024 + kb); \
        ra1 = *(const uint4*)(Qh8 + (size_t)(q0 + 64 + r0) * 1024 + kb); \
        rb0 = *(const uint4*)(Bsrc + (size_t)((n0) + r0) * 1024 + kb); \
        rb1 = *(const uint4*)(Bsrc + (size_t)((n0) + 64 + r0) * 1024 + kb); \
    } while (0)
#define MB_STS(buf) do { \
        char* dA = sm + (buf) * MB_BUF + r0 * 80 + cseg; \
        *(uint4*)dA = ra0; *(uint4*)(dA + 64 * 80) = ra1; \
        char* dB = sm + (buf) * MB_BUF + 10240 + r0 * 80 + cseg; \
        *(uint4*)dB = rb0; *(uint4*)(dB + 64 * 80) = rb1; \
    } while (0)

    for (int nt = 0; nt < 4; nt++) {
        int n0 = nt * 128;
        float d[2][8][4];
#pragma unroll
        for (int a = 0; a < 2; a++)
#pragma unroll
            for (int b = 0; b < 8; b++)
#pragma unroll
                for (int k = 0; k < 4; k++) d[a][b][k] = 0.f;
        MB_LOAD(0, n0); MB_STS(0);
        __syncthreads();
        for (int c = 0; c < 32; c++) {
            int cur = c & 1;
            if (c < 31) MB_LOAD(c + 1, n0);
            uint32_t baseA = smb + cur * MB_BUF;
            uint32_t baseB = baseA + 10240;
#pragma unroll
            for (int ks = 0; ks < 2; ks++) {
                uint32_t afr[2][4], bfr[8][2], r4[4];
#pragma unroll
                for (int mi = 0; mi < 2; mi++)
                    ldm4(afr[mi], baseA + (warp_m + mi * 16 + (lane & 15)) * 80 + (lane >> 4) * 16 + ks * 32);
#pragma unroll
                for (int j = 0; j < 4; j++) {
                    ldm4(r4, baseB + (warp_n + j * 16 + ((lane >> 4) & 1) * 8 + (lane & 7)) * 80 + ((lane >> 3) & 1) * 16 + ks * 32);
                    bfr[2 * j][0] = r4[0]; bfr[2 * j][1] = r4[1];
                    bfr[2 * j + 1][0] = r4[2]; bfr[2 * j + 1][1] = r4[3];
                }
#pragma unroll
                for (int mi = 0; mi < 2; mi++)
#pragma unroll
                    for (int ni = 0; ni < 8; ni++)
                        mma16816(d[mi][ni], afr[mi], bfr[ni]);
            }
            if (c < 31) MB_STS(1 - cur);
            __syncthreads();
        }
#pragma unroll
        for (int mi = 0; mi < 2; mi++)
#pragma unroll
            for (int h = 0; h < 2; h++) {
                int row = q0 + warp_m + mi * 16 + h * 8 + (lane >> 2);
                float a = 0.f;
#pragma unroll
                for (int ni = 0; ni < 8; ni++) {
                    int col = n0 + warp_n + ni * 8 + 2 * (lane & 3);
                    float2 qv = *(const float2*)&Q[(size_t)row * D + col];
                    float v0 = 2.f * qv.x - __bfloat162float(__float2bfloat16(qv.x));
                    float v1 = 2.f * qv.y - __bfloat162float(__float2bfloat16(qv.y));
                    a += d[mi][ni][2 * h] * v0 + d[mi][ni][2 * h + 1] * v1;
                }
                accS[mi * 2 + h] += a;
            }
    }
#pragma unroll
    for (int i = 0; i < 4; i++) {
        accS[i] += __shfl_xor_sync(0xffffffffu, accS[i], 1);
        accS[i] += __shfl_xor_sync(0xffffffffu, accS[i], 2);
    }
    if ((lane & 3) == 0) {
#pragma unroll
        for (int mi = 0; mi < 2; mi++)
#pragma unroll
            for (int h = 0; h < 2; h++)
                sRow[warp_m + mi * 16 + h * 8 + (lane >> 2)][wid & 1] = accS[mi * 2 + h];
    }
    __syncthreads();
    if (tid < 128) g_S[cls][q0 + tid] = sRow[tid][0] + sRow[tid][1];
#undef MB_LOAD
#undef MB_STS
}

// ---------------- K7: logits ----------------
__global__ void k_final(const float* __restrict__ Q, float* __restrict__ out, int nq) {
    int w = (blockIdx.x * blockDim.x + threadIdx.x) >> 5;
    int lane = threadIdx.x & 31;
    if (w >= nq) return;
    float qw0 = 0.f, qw1 = 0.f;
    for (int k = lane; k < D; k += 32) {
        float qk = Q[w * D + k];
        qw0 += qk * g_w[0][k];
        qw1 += qk * g_w[1][k];
    }
    for (int o = 16; o > 0; o >>= 1) {
        qw0 += __shfl_down_sync(0xffffffffu, qw0, o);
        qw1 += __shfl_down_sync(0xffffffffu, qw1, o);
    }
    if (lane == 0) {
        out[w * 2 + 0] = -(g_S[0][w] - 2.f * qw0 + g_z.b[0]);
        out[w * 2 + 1] = -(g_S[1][w] - 2.f * qw1 + g_z.b[1]);
    }
}

// ---------------- launch ----------------
extern "C" void kernel_launch(void* const* d_in, const int* in_sizes, int n_in,
                              void* d_out, int out_size) {
    const float*        SF   = (const float*)d_in[0];
    const unsigned int* labw = (const unsigned int*)d_in[1];
    const float*        Q    = (const float*)d_in[2];
    float*              out  = (float*)d_out;
    int nq = in_sizes[2] / D;  // 16384

    void* pZ;
    float *pT, *pG, *pG0, *pX0, *pX1;
    __nv_bfloat16 *pQh, *pAh, *pAl, *pTh, *pTl, *pXh0, *pXl0, *pXh1, *pXl1;
    cudaGetSymbolAddress(&pZ, g_z);
    cudaGetSymbolAddress((void**)&pT, g_T);
    cudaGetSymbolAddress((void**)&pG, g_G);
    cudaGetSymbolAddress((void**)&pG0, g_G0);
    cudaGetSymbolAddress((void**)&pX0, g_NS0);
    cudaGetSymbolAddress((void**)&pX1, g_NS1);
    cudaGetSymbolAddress((void**)&pQh, g_Qh);
    cudaGetSymbolAddress((void**)&pAh, g_Ah);
    cudaGetSymbolAddress((void**)&pAl, g_Al);
    cudaGetSymbolAddress((void**)&pTh, g_Th);
    cudaGetSymbolAddress((void**)&pTl, g_Tl);
    cudaGetSymbolAddress((void**)&pXh0, g_X0h);
    cudaGetSymbolAddress((void**)&pXl0, g_X0l);
    cudaGetSymbolAddress((void**)&pXh1, g_X1h);
    cudaGetSymbolAddress((void**)&pXl1, g_X1l);
    float* pFro = (float*)((char*)pZ + offsetof(ZBlk, fro));
    cudaFuncSetAttribute(k_main_mma, cudaFuncAttributeMaxDynamicSharedMemorySize, 2 * MB_BUF);

    cudaMemsetAsync(pZ, 0, sizeof(ZBlk));
    k_pre<<<256, 256>>>(SF, labw);
    k_gram_tc<<<dim3(8, 8), 256>>>(pTh, pTl, pG, pG0, pT, pX0, pX0 + DD, pT + DD);
    k_assemble<<<dim3(DD / 256, 2), 256>>>();

    dim3 gns(8, 8, 2);
    // spectral bound: T = A@A (1-pass), X1 = T@T with fused fro(A^4)^2 accumulation
    gemm_ns<<<gns, 256>>>(pAh, pAl, pAh, pAl, nullptr, pT, pTh, pTl, 0, 16, 0, nullptr);
    gemm_ns<<<gns, 256>>>(pTh, pTl, pTh, pTl, nullptr, pX1, pXh1, pXl1, 0, 16, 1, pFro);
    k_init<<<dim3(DD / 256, 2), 256>>>();

    float *X = pX0, *Xn = pX1;
    __nv_bfloat16 *Xh = pXh0, *Xl = pXl0, *Xnh = pXh1, *Xnl = pXl1;
    for (int it = 0; it < NIT_CHEAP + NIT_FULL; it++) {
        int nch = (it < NIT_CHEAP) ? 16 : 48;
        gemm_ns<<<gns, 256>>>(Xh, Xl, pAh, pAl, nullptr, pT, pTh, pTl, 0, nch, 0, nullptr);
        gemm_ns<<<gns, 256>>>(pTh, pTl, Xh, Xl, X, Xn, Xnh, Xnl, 1, nch, 0, nullptr);
        float* tf = X; X = Xn; Xn = tf;
        __nv_bfloat16* tb;
        tb = Xh; Xh = Xnh; Xnh = tb;
        tb = Xl; Xl = Xnl; Xnl = tb;
    }
    // X / Xh / Xl hold P_c and its bf16 split

    k_wb<<<dim3(2, 8), 256>>>(X);
    k_split<<<(nq * D) / 1024, 256>>>(Q, pQh);
    k_main_mma<<<dim3(nq / 128, 2), 256, 2 * MB_BUF>>>(Q, pQh, Xh, Xl);
    k_final<<<(nq * 32 + 255) / 256, 256>>>(Q, out, nq);
}